// round 15
// baseline (speedup 1.0000x reference)
#include <cuda_runtime.h>
#include <math.h>

typedef unsigned long long ull;

// ---------------------------------------------------------------------------
// Scratch (device globals; allocations forbidden).
// ---------------------------------------------------------------------------
#define VS 345600
#define PS 1881600
__device__ float g_bufA[3 * VS];
__device__ float g_bufB[3 * VS];
__device__ float g_patch[3 * PS];   // streams: center | mid | rad
__device__ float g_wpad[96 * 148];

#define ABSM 0x7FFFFFFF7FFFFFFFULL
#define M1   0xBF800000BF800000ULL

// ---------------------------------------------------------------------------
// f32x2 packed helpers (sm_103a)
// ---------------------------------------------------------------------------
__device__ __forceinline__ ull pk2(float lo, float hi) {
    ull r; asm("mov.b64 %0, {%1,%2};" : "=l"(r) : "f"(lo), "f"(hi)); return r;
}
__device__ __forceinline__ void upk2(ull v, float& lo, float& hi) {
    asm("mov.b64 {%0,%1}, %2;" : "=f"(lo), "=f"(hi) : "l"(v));
}
__device__ __forceinline__ ull fma2(ull a, ull b, ull c) {
    ull r; asm("fma.rn.f32x2 %0, %1, %2, %3;" : "=l"(r) : "l"(a), "l"(b), "l"(c)); return r;
}
__device__ __forceinline__ ull mul2(ull a, ull b) {
    ull r; asm("mul.rn.f32x2 %0, %1, %2;" : "=l"(r) : "l"(a), "l"(b)); return r;
}
__device__ __forceinline__ ull add2(ull a, ull b) {
    ull r; asm("add.rn.f32x2 %0, %1, %2;" : "=l"(r) : "l"(a), "l"(b)); return r;
}
__device__ __forceinline__ float root8(float s) { return sqrtf(sqrtf(sqrtf(s))); }

// All-packed bound-distance accumulation (13 fma-pipe ops / HALF).
#define HALF(W, VC, MD, RD, AC, AL, AH) {                               \
        ull dc = fma2(W, M1, VC);                                       \
        ull s  = mul2(dc, dc); s = mul2(s, s); AC = fma2(s, s, AC);     \
        ull a  = fma2(W, M1, MD);                                       \
        ull aa = a & ABSM;                                              \
        ull dh = add2(aa, RD);                                          \
        s = mul2(dh, dh); s = mul2(s, s); AH = fma2(s, s, AH);          \
        ull t  = fma2(RD, M1, aa);                                      \
        float t0, t1; upk2(t, t0, t1);                                  \
        ull v  = pk2(fmaxf(t0, 0.f), fmaxf(t1, 0.f));                   \
        s = mul2(v, v); s = mul2(s, s); AL = fma2(s, s, AL); }

// One 4-channel x 4-f-element compute body (weights from smem, fs const).
#define BODY(Q, C4, M4, R4) {                                           \
        const ull c01 = pk2(C4.x, C4.y), c23 = pk2(C4.z, C4.w);         \
        const ull m01 = pk2(M4.x, M4.y), m23 = pk2(M4.z, M4.w);         \
        const ull r01 = pk2(R4.x, R4.y), r23 = pk2(R4.z, R4.w);         \
        _Pragma("unroll")                                               \
        for (int ch = 0; ch < 4; ch++) {                                \
            const float4 wv = wq[(Q) + ch * fs];                        \
            const ull w01 = pk2(wv.x, wv.y), w23 = pk2(wv.z, wv.w);     \
            HALF(w01, c01, m01, r01, A[ch*3], A[ch*3+1], A[ch*3+2]);    \
            HALF(w23, c23, m23, r23, A[ch*3], A[ch*3+1], A[ch*3+2]);    \
        } }

// ---------------------------------------------------------------------------
// prep1: conv1 im2col of (center, mid, rad) from real lower/upper inputs
// (Fp 147->148 zero-pad) + conv1 weight pad.
// ---------------------------------------------------------------------------
#define P1_IM2COL (16 * 225 * 148)
#define P1_WPAD   (96 * 148)
__global__ void __launch_bounds__(256) prep1_kernel(
    const float* __restrict__ ic, const float* __restrict__ il, const float* __restrict__ ih,
    const float* __restrict__ w1,
    float* __restrict__ oc, float* __restrict__ om, float* __restrict__ orr,
    float* __restrict__ wp)
{
    const int idx = blockIdx.x * blockDim.x + threadIdx.x;
    if (idx < P1_IM2COL) {
        const int f  = idx % 148;
        const int bl = idx / 148;
        const int l  = bl % 225;
        const int b  = bl / 225;
        float vc = 0.f, vm = 0.f, vr = 0.f;
        if (f < 147) {
            const int c  = f / 49;
            const int r  = f - c * 49;
            const int ky = r / 7, kx = r - (r / 7) * 7;
            const int oy = l / 15, ox = l - (l / 15) * 15;
            const int iy = oy * 2 - 2 + ky;
            const int ix = ox * 2 - 2 + kx;
            if ((unsigned)iy < 32u && (unsigned)ix < 32u) {
                const int si = ((b * 3 + c) * 32 + iy) * 32 + ix;
                const float lv = il[si], hv = ih[si];
                vc = ic[si]; vm = 0.5f * (lv + hv); vr = 0.5f * (hv - lv);
            }
        }
        oc[idx] = vc; om[idx] = vm; orr[idx] = vr;
    } else if (idx < P1_IM2COL + P1_WPAD) {
        const int j = idx - P1_IM2COL;
        const int f = j % 148, o = j / 148;
        wp[j] = (f < 147) ? w1[o * 147 + f] : 0.f;
    }
}

// ---------------------------------------------------------------------------
// 3x3/s2 maxpool on RAW 8th-power sums -> root8 on pooled maxima (exact)
// -> (c, mid, rad).
// ---------------------------------------------------------------------------
__global__ void __launch_bounds__(256) pool3s_kernel(
    const float* __restrict__ ic, const float* __restrict__ il, const float* __restrict__ ih,
    float* __restrict__ oc, float* __restrict__ om, float* __restrict__ orr,
    int NC, int H, int W, int h, int w)
{
    const int i = blockIdx.x * blockDim.x + threadIdx.x;
    if (i >= NC * h * w) return;
    const int x = i % w;
    const int y = (i / w) % h;
    const int n = i / (w * h);
    const int base = (n * H + y * 2) * W + x * 2;
    float m0 = 0.f, m1 = 0.f, m2 = 0.f;   // sums are >= 0
#pragma unroll
    for (int ky = 0; ky < 3; ky++)
#pragma unroll
        for (int kx = 0; kx < 3; kx++) {
            const int si = base + ky * W + kx;
            m0 = fmaxf(m0, ic[si]);
            m1 = fmaxf(m1, il[si]);
            m2 = fmaxf(m2, ih[si]);
        }
    const float cv = root8(m0);
    const float lv = root8(m1);
    const float hv = root8(m2);
    oc[i] = cv; om[i] = 0.5f * (lv + hv); orr[i] = 0.5f * (hv - lv);
}

// ---------------------------------------------------------------------------
// Window gather: one thread per (bl, c) copies its entire KxK window for all
// three streams (contiguous K*K stores; unrolled; ~2.5x fewer instrs than
// thread-per-element).
// ---------------------------------------------------------------------------
template<int C, int HW, int K, int PAD>
__global__ void __launch_bounds__(256) wgather_kernel(
    const float* __restrict__ ic, const float* __restrict__ im, const float* __restrict__ ir,
    float* __restrict__ oc, float* __restrict__ om, float* __restrict__ orr)
{
    constexpr int KK = K * K;
    constexpr int Fp = C * KK;
    constexpr int L  = HW * HW;
    constexpr int N  = 16 * L * C;
    const int idx = blockIdx.x * blockDim.x + threadIdx.x;
    if (idx >= N) return;
    const int c  = idx % C;
    const int bl = idx / C;
    const int l  = bl % L;
    const int b  = bl / L;
    const int oy = l / HW, ox = l % HW;

    const int plane = (b * C + c) * L;
    const float* sc = ic + plane;
    const float* sm = im + plane;
    const float* sr = ir + plane;
    const size_t dbase = (size_t)bl * Fp + c * KK;
    float* dc = oc + dbase;
    float* dm = om + dbase;
    float* dr = orr + dbase;

#pragma unroll
    for (int ky = 0; ky < K; ky++) {
        const int py = oy - PAD + ky;
        const bool yok = (unsigned)py < (unsigned)HW;
#pragma unroll
        for (int kx = 0; kx < K; kx++) {
            const int px = ox - PAD + kx;
            const bool ok = yok && ((unsigned)px < (unsigned)HW);
            const int si = py * HW + px;
            const int di = ky * K + kx;
            dc[di] = ok ? sc[si] : 0.f;
            dm[di] = ok ? sm[si] : 0.f;
            dr[di] = ok ? sr[si] : 0.f;
        }
    }
}

// ---------------------------------------------------------------------------
// Packed NormDist (L8) conv, fully templated <FP, OUTMODE, MINB>.
// Block = 8 warps, 1 og-quad of weights in smem, 8 bl per block.
// grid = (O/4, BL/8). OUTMODE 0: RAW sums; 1: (c, mid, rad) with root8.
// ---------------------------------------------------------------------------
template<int FP, int OUTMODE, int MINB>
__global__ void __launch_bounds__(256, MINB) normdist_conv_t(
    const float* __restrict__ pc, const float* __restrict__ pm, const float* __restrict__ pr,
    const float* __restrict__ wgt,
    float* __restrict__ o0, float* __restrict__ o1, float* __restrict__ o2,
    int L, int O)
{
    extern __shared__ float swd[];
    constexpr int fs = FP >> 2;
    const int tid = threadIdx.x;
    {
        const float4* src = (const float4*)(wgt + (size_t)blockIdx.x * 4 * FP);
        float4* dst = (float4*)swd;
#pragma unroll
        for (int i = tid; i < FP; i += 256) dst[i] = src[i];
    }
    __syncthreads();

    const int w    = tid >> 5;
    const int lane = tid & 31;
    const int bl   = blockIdx.y * 8 + w;

    const float4* pc4 = (const float4*)(pc + (size_t)bl * FP);
    const float4* pm4 = (const float4*)(pm + (size_t)bl * FP);
    const float4* pr4 = (const float4*)(pr + (size_t)bl * FP);
    const float4* wq  = (const float4*)swd;

    ull A[12];
#pragma unroll
    for (int i = 0; i < 12; i++) A[i] = 0;

    if (fs > 64) {
        int q = lane;
        for (; q + 32 < fs; q += 64) {
            const float4 ca = pc4[q],      ma = pm4[q],      ra = pr4[q];
            const float4 cb = pc4[q + 32], mb = pm4[q + 32], rb = pr4[q + 32];
            BODY(q, ca, ma, ra);
            BODY(q + 32, cb, mb, rb);
        }
        if (q < fs) {
            const float4 ca = pc4[q], ma = pm4[q], ra = pr4[q];
            BODY(q, ca, ma, ra);
        }
    } else {
#pragma unroll
        for (int qq = 0; qq < (fs + 31) / 32; qq++) {
            const int q = qq * 32 + lane;
            if (q < fs) {
                const float4 ca = pc4[q], ma = pm4[q], ra = pr4[q];
                BODY(q, ca, ma, ra);
            }
        }
    }

    float r[12];
#pragma unroll
    for (int i = 0; i < 12; i++) {
        float x0, x1; upk2(A[i], x0, x1); r[i] = x0 + x1;
    }
#pragma unroll
    for (int off = 16; off; off >>= 1)
#pragma unroll
        for (int i = 0; i < 12; i++)
            r[i] += __shfl_xor_sync(0xffffffffu, r[i], off);

    if (lane < 4) {
        const int b = bl / L, l = bl - (bl / L) * L;
        const int o = blockIdx.x * 4 + lane;
        const size_t ob = ((size_t)b * O + o) * L + l;
        if (OUTMODE == 0) {
            o0[ob] = r[3 * lane];
            o1[ob] = r[3 * lane + 1];
            o2[ob] = r[3 * lane + 2];
        } else {
            const float oc = root8(r[3 * lane]);
            const float ol = root8(r[3 * lane + 1]);
            const float oh = root8(r[3 * lane + 2]);
            o0[ob] = oc;
            o1[ob] = 0.5f * (ol + oh);
            o2[ob] = 0.5f * (oh - ol);
        }
    }
}

// ---------------------------------------------------------------------------
// Interval-bound linear on (c, m, r) streams, 8 batches per warp
// (halves weight traffic vs 4). mode 0: relu, outputs (c, m, r);
// mode 1: final (-c, -u, -l).
// ---------------------------------------------------------------------------
__global__ void __launch_bounds__(256) bound_linear8_kernel(
    const float* __restrict__ inc, const float* __restrict__ inm, const float* __restrict__ inr,
    const float* __restrict__ Wm, const float* __restrict__ bias,
    float* __restrict__ o0, float* __restrict__ o1, float* __restrict__ o2,
    int B, int IN, int OUT, int mode)
{
    const int warp = (blockIdx.x * blockDim.x + threadIdx.x) >> 5;
    const int lane = threadIdx.x & 31;
    const int BG = B >> 3;
    if (warp >= OUT * BG) return;
    const int o  = warp % OUT;
    const int bg = warp / OUT;
    const int b0 = bg * 8;

    const float4* w4 = (const float4*)(Wm + (size_t)o * IN);
    const float4* c4 = (const float4*)(inc + (size_t)b0 * IN);
    const float4* m4 = (const float4*)(inm + (size_t)b0 * IN);
    const float4* r4 = (const float4*)(inr + (size_t)b0 * IN);
    const int n4 = IN >> 2;

    float r[24];
#pragma unroll
    for (int i = 0; i < 24; i++) r[i] = 0.f;

    for (int k = lane; k < n4; k += 32) {
        const float4 wv = w4[k];
        const float awx = fabsf(wv.x), awy = fabsf(wv.y), awz = fabsf(wv.z), aww = fabsf(wv.w);
#pragma unroll
        for (int j = 0; j < 8; j++) {
            const float4 cv = c4[k + (size_t)j * n4];
            const float4 mv = m4[k + (size_t)j * n4];
            const float4 rv = r4[k + (size_t)j * n4];
            float sc = r[j * 3], sm = r[j * 3 + 1], sr = r[j * 3 + 2];
            sc = fmaf(cv.x, wv.x, sc); sc = fmaf(cv.y, wv.y, sc);
            sc = fmaf(cv.z, wv.z, sc); sc = fmaf(cv.w, wv.w, sc);
            sm = fmaf(mv.x, wv.x, sm); sm = fmaf(mv.y, wv.y, sm);
            sm = fmaf(mv.z, wv.z, sm); sm = fmaf(mv.w, wv.w, sm);
            sr = fmaf(rv.x, awx, sr); sr = fmaf(rv.y, awy, sr);
            sr = fmaf(rv.z, awz, sr); sr = fmaf(rv.w, aww, sr);
            r[j * 3] = sc; r[j * 3 + 1] = sm; r[j * 3 + 2] = sr;
        }
    }
#pragma unroll
    for (int off = 16; off; off >>= 1)
#pragma unroll
        for (int i = 0; i < 24; i++)
            r[i] += __shfl_xor_sync(0xffffffffu, r[i], off);

    if (lane < 8) {
        const int b = b0 + lane;
        const float sc = r[lane * 3], sm = r[lane * 3 + 1], sr = r[lane * 3 + 2];
        const size_t idx = (size_t)b * OUT + o;
        if (mode == 0) {
            const float lr = fmaxf(sm - sr, 0.f);
            const float hr = fmaxf(sm + sr, 0.f);
            o0[idx] = fmaxf(sc, 0.f);
            o1[idx] = 0.5f * (lr + hr);
            o2[idx] = 0.5f * (hr - lr);
        } else {
            const float bv  = bias[o];
            const float oc  = sc + bv;
            const float mid = sm + bv;
            o0[idx] = -oc;            // -center
            o1[idx] = -(mid + sr);    // -upper
            o2[idx] = -(mid - sr);    // -lower
        }
    }
}

// ---------------------------------------------------------------------------
// Host orchestration (graph-capturable: launches only).
// ---------------------------------------------------------------------------
static inline int cdiv(int a, int b) { return (a + b - 1) / b; }

extern "C" void kernel_launch(void* const* d_in, const int* in_sizes, int n_in,
                              void* d_out, int out_size)
{
    const float* x   = (const float*)d_in[0];
    const float* lo  = (const float*)d_in[1];
    const float* hi  = (const float*)d_in[2];
    const float* w1  = (const float*)d_in[3];
    const float* w2  = (const float*)d_in[4];
    const float* w3  = (const float*)d_in[5];
    const float* w4  = (const float*)d_in[6];
    const float* w5  = (const float*)d_in[7];
    const float* fw1 = (const float*)d_in[8];
    const float* fw2 = (const float*)d_in[9];
    const float* fw3 = (const float*)d_in[10];
    const float* fb3 = (const float*)d_in[11];
    float* out = (float*)d_out;

    cudaFuncSetAttribute(normdist_conv_t<2400, 0, 3>,
                         cudaFuncAttributeMaxDynamicSharedMemorySize, 56 * 1024);
    cudaFuncSetAttribute(normdist_conv_t<2304, 1, 3>,
                         cudaFuncAttributeMaxDynamicSharedMemorySize, 56 * 1024);
    cudaFuncSetAttribute(normdist_conv_t<3456, 1, 3>,
                         cudaFuncAttributeMaxDynamicSharedMemorySize, 56 * 1024);

    float *A, *Bf, *P, *WP;
    cudaGetSymbolAddress((void**)&A,  g_bufA);
    cudaGetSymbolAddress((void**)&Bf, g_bufB);
    cudaGetSymbolAddress((void**)&P,  g_patch);
    cudaGetSymbolAddress((void**)&WP, g_wpad);
    float *A0 = A,  *A1 = A  + VS, *A2 = A  + 2 * VS;
    float *B0 = Bf, *B1 = Bf + VS, *B2 = Bf + 2 * VS;
    float *P0 = P,  *P1 = P  + PS, *P2 = P  + 2 * PS;

    // (1) prep: conv1 patches (c,m,r) from real lower/upper + weight pad
    prep1_kernel<<<cdiv(P1_IM2COL + P1_WPAD, 256), 256>>>(
        x, lo, hi, w1, P0, P1, P2, WP);

    // (2) conv1: -> [16,96,15,15] RAW sums
    normdist_conv_t<148, 0, 4><<<dim3(24, 450), 256, 4 * 148 * 4>>>(
        P0, P1, P2, WP, A0, A1, A2, 225, 96);

    // (3) pool1 (max raw, root8): -> (c,m,r) [16,96,7,7]
    pool3s_kernel<<<cdiv(16 * 96 * 49, 256), 256>>>(
        A0, A1, A2, B0, B1, B2, 16 * 96, 15, 15, 7, 7);

    // (4) window gather k=5,p=2: Fp=2400
    wgather_kernel<96, 7, 5, 2><<<cdiv(16 * 49 * 96, 256), 256>>>(
        B0, B1, B2, P0, P1, P2);

    // (5) conv2: -> [16,256,7,7] RAW sums
    normdist_conv_t<2400, 0, 3><<<dim3(64, 98), 256, 4 * 2400 * 4>>>(
        P0, P1, P2, w2, A0, A1, A2, 49, 256);

    // (6) pool2: -> (c,m,r) [16,256,3,3]
    pool3s_kernel<<<cdiv(16 * 256 * 9, 256), 256>>>(
        A0, A1, A2, B0, B1, B2, 16 * 256, 7, 7, 3, 3);

    // (7) window gather k=3,p=1: Fp=2304
    wgather_kernel<256, 3, 3, 1><<<cdiv(16 * 9 * 256, 256), 256>>>(
        B0, B1, B2, P0, P1, P2);

    // (8) conv3: -> [16,384,3,3] as (c,m,r)
    normdist_conv_t<2304, 1, 3><<<dim3(96, 18), 256, 4 * 2304 * 4>>>(
        P0, P1, P2, w3, A0, A1, A2, 9, 384);

    // (9) window gather k=3,p=1: Fp=3456
    wgather_kernel<384, 3, 3, 1><<<cdiv(16 * 9 * 384, 256), 256>>>(
        A0, A1, A2, P0, P1, P2);

    // (10) conv4: -> [16,384,3,3] as (c,m,r)
    normdist_conv_t<3456, 1, 3><<<dim3(96, 18), 256, 4 * 3456 * 4>>>(
        P0, P1, P2, w4, B0, B1, B2, 9, 384);

    // (11) window gather: Fp=3456
    wgather_kernel<384, 3, 3, 1><<<cdiv(16 * 9 * 384, 256), 256>>>(
        B0, B1, B2, P0, P1, P2);

    // (12) conv5: -> [16,256,3,3] as (c,m,r) == flattened [16,2304]
    normdist_conv_t<3456, 1, 3><<<dim3(64, 18), 256, 4 * 3456 * 4>>>(
        P0, P1, P2, w5, A0, A1, A2, 9, 256);

    // (13) fc1: 2304 -> 1024 (+relu), (c,m,r), 8 batches/warp
    bound_linear8_kernel<<<cdiv(1024 * 2 * 32, 256), 256>>>(
        A0, A1, A2, fw1, (const float*)nullptr, B0, B1, B2, 16, 2304, 1024, 0);
    // (14) fc2: 1024 -> 512 (+relu)
    bound_linear8_kernel<<<cdiv(512 * 2 * 32, 256), 256>>>(
        B0, B1, B2, fw2, (const float*)nullptr, A0, A1, A2, 16, 1024, 512, 0);
    // (15) fc3: 512 -> 10 (+bias): d_out = [-c | -u | -l]
    bound_linear8_kernel<<<cdiv(10 * 2 * 32, 256), 256>>>(
        A0, A1, A2, fw3, fb3, out, out + 160, out + 320, 16, 512, 10, 1);
}

// round 16
// speedup vs baseline: 1.0027x; 1.0027x over previous
#include <cuda_runtime.h>
#include <math.h>

typedef unsigned long long ull;

// ---------------------------------------------------------------------------
// Scratch (device globals; allocations forbidden).
// ---------------------------------------------------------------------------
#define VS 345600
#define PS 1881600
__device__ float g_bufA[3 * VS];
__device__ float g_bufB[3 * VS];
__device__ float g_patch[3 * PS];   // streams: center | mid | rad
__device__ float g_wpad[96 * 148];

#define ABSM 0x7FFFFFFF7FFFFFFFULL
#define M1   0xBF800000BF800000ULL

// ---------------------------------------------------------------------------
// f32x2 packed helpers (sm_103a)
// ---------------------------------------------------------------------------
__device__ __forceinline__ ull pk2(float lo, float hi) {
    ull r; asm("mov.b64 %0, {%1,%2};" : "=l"(r) : "f"(lo), "f"(hi)); return r;
}
__device__ __forceinline__ void upk2(ull v, float& lo, float& hi) {
    asm("mov.b64 {%0,%1}, %2;" : "=f"(lo), "=f"(hi) : "l"(v));
}
__device__ __forceinline__ ull fma2(ull a, ull b, ull c) {
    ull r; asm("fma.rn.f32x2 %0, %1, %2, %3;" : "=l"(r) : "l"(a), "l"(b), "l"(c)); return r;
}
__device__ __forceinline__ ull mul2(ull a, ull b) {
    ull r; asm("mul.rn.f32x2 %0, %1, %2;" : "=l"(r) : "l"(a), "l"(b)); return r;
}
__device__ __forceinline__ ull add2(ull a, ull b) {
    ull r; asm("add.rn.f32x2 %0, %1, %2;" : "=l"(r) : "l"(a), "l"(b)); return r;
}
__device__ __forceinline__ float root8(float s) { return sqrtf(sqrtf(sqrtf(s))); }

// All-packed bound-distance accumulation (13 fma-pipe ops / HALF).
#define HALF(W, VC, MD, RD, AC, AL, AH) {                               \
        ull dc = fma2(W, M1, VC);                                       \
        ull s  = mul2(dc, dc); s = mul2(s, s); AC = fma2(s, s, AC);     \
        ull a  = fma2(W, M1, MD);                                       \
        ull aa = a & ABSM;                                              \
        ull dh = add2(aa, RD);                                          \
        s = mul2(dh, dh); s = mul2(s, s); AH = fma2(s, s, AH);          \
        ull t  = fma2(RD, M1, aa);                                      \
        float t0, t1; upk2(t, t0, t1);                                  \
        ull v  = pk2(fmaxf(t0, 0.f), fmaxf(t1, 0.f));                   \
        s = mul2(v, v); s = mul2(s, s); AL = fma2(s, s, AL); }

// One 4-channel x 4-f-element compute body (weights from smem, fs const).
#define BODY(Q, C4, M4, R4) {                                           \
        const ull c01 = pk2(C4.x, C4.y), c23 = pk2(C4.z, C4.w);         \
        const ull m01 = pk2(M4.x, M4.y), m23 = pk2(M4.z, M4.w);         \
        const ull r01 = pk2(R4.x, R4.y), r23 = pk2(R4.z, R4.w);         \
        _Pragma("unroll")                                               \
        for (int ch = 0; ch < 4; ch++) {                                \
            const float4 wv = wq[(Q) + ch * fs];                        \
            const ull w01 = pk2(wv.x, wv.y), w23 = pk2(wv.z, wv.w);     \
            HALF(w01, c01, m01, r01, A[ch*3], A[ch*3+1], A[ch*3+2]);    \
            HALF(w23, c23, m23, r23, A[ch*3], A[ch*3+1], A[ch*3+2]);    \
        } }

// ---------------------------------------------------------------------------
// prep1: conv1 im2col of (center, mid, rad) from real lower/upper inputs
// (Fp 147->148 zero-pad) + conv1 weight pad.
// ---------------------------------------------------------------------------
#define P1_IM2COL (16 * 225 * 148)
#define P1_WPAD   (96 * 148)
__global__ void __launch_bounds__(256) prep1_kernel(
    const float* __restrict__ ic, const float* __restrict__ il, const float* __restrict__ ih,
    const float* __restrict__ w1,
    float* __restrict__ oc, float* __restrict__ om, float* __restrict__ orr,
    float* __restrict__ wp)
{
    const int idx = blockIdx.x * blockDim.x + threadIdx.x;
    if (idx < P1_IM2COL) {
        const int f  = idx % 148;
        const int bl = idx / 148;
        const int l  = bl % 225;
        const int b  = bl / 225;
        float vc = 0.f, vm = 0.f, vr = 0.f;
        if (f < 147) {
            const int c  = f / 49;
            const int r  = f - c * 49;
            const int ky = r / 7, kx = r - (r / 7) * 7;
            const int oy = l / 15, ox = l - (l / 15) * 15;
            const int iy = oy * 2 - 2 + ky;
            const int ix = ox * 2 - 2 + kx;
            if ((unsigned)iy < 32u && (unsigned)ix < 32u) {
                const int si = ((b * 3 + c) * 32 + iy) * 32 + ix;
                const float lv = il[si], hv = ih[si];
                vc = ic[si]; vm = 0.5f * (lv + hv); vr = 0.5f * (hv - lv);
            }
        }
        oc[idx] = vc; om[idx] = vm; orr[idx] = vr;
    } else if (idx < P1_IM2COL + P1_WPAD) {
        const int j = idx - P1_IM2COL;
        const int f = j % 148, o = j / 148;
        wp[j] = (f < 147) ? w1[o * 147 + f] : 0.f;
    }
}

// ---------------------------------------------------------------------------
// 3x3/s2 maxpool on RAW 8th-power sums -> root8 on pooled maxima (exact)
// -> (c, mid, rad).
// ---------------------------------------------------------------------------
__global__ void __launch_bounds__(256) pool3s_kernel(
    const float* __restrict__ ic, const float* __restrict__ il, const float* __restrict__ ih,
    float* __restrict__ oc, float* __restrict__ om, float* __restrict__ orr,
    int NC, int H, int W, int h, int w)
{
    const int i = blockIdx.x * blockDim.x + threadIdx.x;
    if (i >= NC * h * w) return;
    const int x = i % w;
    const int y = (i / w) % h;
    const int n = i / (w * h);
    const int base = (n * H + y * 2) * W + x * 2;
    float m0 = 0.f, m1 = 0.f, m2 = 0.f;   // sums are >= 0
#pragma unroll
    for (int ky = 0; ky < 3; ky++)
#pragma unroll
        for (int kx = 0; kx < 3; kx++) {
            const int si = base + ky * W + kx;
            m0 = fmaxf(m0, ic[si]);
            m1 = fmaxf(m1, il[si]);
            m2 = fmaxf(m2, ih[si]);
        }
    const float cv = root8(m0);
    const float lv = root8(m1);
    const float hv = root8(m2);
    oc[i] = cv; om[i] = 0.5f * (lv + hv); orr[i] = 0.5f * (hv - lv);
}

// ---------------------------------------------------------------------------
// Window gather: one thread per (bl, c) copies its entire KxK window for all
// three streams (contiguous K*K stores; unrolled; ~2.5x fewer instrs than
// thread-per-element).
// ---------------------------------------------------------------------------
template<int C, int HW, int K, int PAD>
__global__ void __launch_bounds__(256) wgather_kernel(
    const float* __restrict__ ic, const float* __restrict__ im, const float* __restrict__ ir,
    float* __restrict__ oc, float* __restrict__ om, float* __restrict__ orr)
{
    constexpr int KK = K * K;
    constexpr int Fp = C * KK;
    constexpr int L  = HW * HW;
    constexpr int N  = 16 * L * C;
    const int idx = blockIdx.x * blockDim.x + threadIdx.x;
    if (idx >= N) return;
    const int c  = idx % C;
    const int bl = idx / C;
    const int l  = bl % L;
    const int b  = bl / L;
    const int oy = l / HW, ox = l % HW;

    const int plane = (b * C + c) * L;
    const float* sc = ic + plane;
    const float* sm = im + plane;
    const float* sr = ir + plane;
    const size_t dbase = (size_t)bl * Fp + c * KK;
    float* dc = oc + dbase;
    float* dm = om + dbase;
    float* dr = orr + dbase;

#pragma unroll
    for (int ky = 0; ky < K; ky++) {
        const int py = oy - PAD + ky;
        const bool yok = (unsigned)py < (unsigned)HW;
#pragma unroll
        for (int kx = 0; kx < K; kx++) {
            const int px = ox - PAD + kx;
            const bool ok = yok && ((unsigned)px < (unsigned)HW);
            const int si = py * HW + px;
            const int di = ky * K + kx;
            dc[di] = ok ? sc[si] : 0.f;
            dm[di] = ok ? sm[si] : 0.f;
            dr[di] = ok ? sr[si] : 0.f;
        }
    }
}

// ---------------------------------------------------------------------------
// Packed NormDist (L8) conv, fully templated <FP, OUTMODE, MINB>.
// Block = 8 warps, 1 og-quad of weights in smem, 8 bl per block.
// grid = (O/4, BL/8). OUTMODE 0: RAW sums; 1: (c, mid, rad) with root8.
// ---------------------------------------------------------------------------
template<int FP, int OUTMODE, int MINB>
__global__ void __launch_bounds__(256, MINB) normdist_conv_t(
    const float* __restrict__ pc, const float* __restrict__ pm, const float* __restrict__ pr,
    const float* __restrict__ wgt,
    float* __restrict__ o0, float* __restrict__ o1, float* __restrict__ o2,
    int L, int O)
{
    extern __shared__ float swd[];
    constexpr int fs = FP >> 2;
    const int tid = threadIdx.x;
    {
        const float4* src = (const float4*)(wgt + (size_t)blockIdx.x * 4 * FP);
        float4* dst = (float4*)swd;
#pragma unroll
        for (int i = tid; i < FP; i += 256) dst[i] = src[i];
    }
    __syncthreads();

    const int w    = tid >> 5;
    const int lane = tid & 31;
    const int bl   = blockIdx.y * 8 + w;

    const float4* pc4 = (const float4*)(pc + (size_t)bl * FP);
    const float4* pm4 = (const float4*)(pm + (size_t)bl * FP);
    const float4* pr4 = (const float4*)(pr + (size_t)bl * FP);
    const float4* wq  = (const float4*)swd;

    ull A[12];
#pragma unroll
    for (int i = 0; i < 12; i++) A[i] = 0;

    if (fs > 64) {
        int q = lane;
        for (; q + 32 < fs; q += 64) {
            const float4 ca = pc4[q],      ma = pm4[q],      ra = pr4[q];
            const float4 cb = pc4[q + 32], mb = pm4[q + 32], rb = pr4[q + 32];
            BODY(q, ca, ma, ra);
            BODY(q + 32, cb, mb, rb);
        }
        if (q < fs) {
            const float4 ca = pc4[q], ma = pm4[q], ra = pr4[q];
            BODY(q, ca, ma, ra);
        }
    } else {
#pragma unroll
        for (int qq = 0; qq < (fs + 31) / 32; qq++) {
            const int q = qq * 32 + lane;
            if (q < fs) {
                const float4 ca = pc4[q], ma = pm4[q], ra = pr4[q];
                BODY(q, ca, ma, ra);
            }
        }
    }

    float r[12];
#pragma unroll
    for (int i = 0; i < 12; i++) {
        float x0, x1; upk2(A[i], x0, x1); r[i] = x0 + x1;
    }
#pragma unroll
    for (int off = 16; off; off >>= 1)
#pragma unroll
        for (int i = 0; i < 12; i++)
            r[i] += __shfl_xor_sync(0xffffffffu, r[i], off);

    if (lane < 4) {
        const int b = bl / L, l = bl - (bl / L) * L;
        const int o = blockIdx.x * 4 + lane;
        const size_t ob = ((size_t)b * O + o) * L + l;
        if (OUTMODE == 0) {
            o0[ob] = r[3 * lane];
            o1[ob] = r[3 * lane + 1];
            o2[ob] = r[3 * lane + 2];
        } else {
            const float oc = root8(r[3 * lane]);
            const float ol = root8(r[3 * lane + 1]);
            const float oh = root8(r[3 * lane + 2]);
            o0[ob] = oc;
            o1[ob] = 0.5f * (ol + oh);
            o2[ob] = 0.5f * (oh - ol);
        }
    }
}

// ---------------------------------------------------------------------------
// Interval-bound linear on (c, m, r) streams, 8 batches per warp
// (halves weight traffic vs 4). mode 0: relu, outputs (c, m, r);
// mode 1: final (-c, -u, -l).
// ---------------------------------------------------------------------------
__global__ void __launch_bounds__(256) bound_linear8_kernel(
    const float* __restrict__ inc, const float* __restrict__ inm, const float* __restrict__ inr,
    const float* __restrict__ Wm, const float* __restrict__ bias,
    float* __restrict__ o0, float* __restrict__ o1, float* __restrict__ o2,
    int B, int IN, int OUT, int mode)
{
    const int warp = (blockIdx.x * blockDim.x + threadIdx.x) >> 5;
    const int lane = threadIdx.x & 31;
    const int BG = B >> 3;
    if (warp >= OUT * BG) return;
    const int o  = warp % OUT;
    const int bg = warp / OUT;
    const int b0 = bg * 8;

    const float4* w4 = (const float4*)(Wm + (size_t)o * IN);
    const float4* c4 = (const float4*)(inc + (size_t)b0 * IN);
    const float4* m4 = (const float4*)(inm + (size_t)b0 * IN);
    const float4* r4 = (const float4*)(inr + (size_t)b0 * IN);
    const int n4 = IN >> 2;

    float r[24];
#pragma unroll
    for (int i = 0; i < 24; i++) r[i] = 0.f;

    for (int k = lane; k < n4; k += 32) {
        const float4 wv = w4[k];
        const float awx = fabsf(wv.x), awy = fabsf(wv.y), awz = fabsf(wv.z), aww = fabsf(wv.w);
#pragma unroll
        for (int j = 0; j < 8; j++) {
            const float4 cv = c4[k + (size_t)j * n4];
            const float4 mv = m4[k + (size_t)j * n4];
            const float4 rv = r4[k + (size_t)j * n4];
            float sc = r[j * 3], sm = r[j * 3 + 1], sr = r[j * 3 + 2];
            sc = fmaf(cv.x, wv.x, sc); sc = fmaf(cv.y, wv.y, sc);
            sc = fmaf(cv.z, wv.z, sc); sc = fmaf(cv.w, wv.w, sc);
            sm = fmaf(mv.x, wv.x, sm); sm = fmaf(mv.y, wv.y, sm);
            sm = fmaf(mv.z, wv.z, sm); sm = fmaf(mv.w, wv.w, sm);
            sr = fmaf(rv.x, awx, sr); sr = fmaf(rv.y, awy, sr);
            sr = fmaf(rv.z, awz, sr); sr = fmaf(rv.w, aww, sr);
            r[j * 3] = sc; r[j * 3 + 1] = sm; r[j * 3 + 2] = sr;
        }
    }
#pragma unroll
    for (int off = 16; off; off >>= 1)
#pragma unroll
        for (int i = 0; i < 24; i++)
            r[i] += __shfl_xor_sync(0xffffffffu, r[i], off);

    if (lane < 8) {
        const int b = b0 + lane;
        const float sc = r[lane * 3], sm = r[lane * 3 + 1], sr = r[lane * 3 + 2];
        const size_t idx = (size_t)b * OUT + o;
        if (mode == 0) {
            const float lr = fmaxf(sm - sr, 0.f);
            const float hr = fmaxf(sm + sr, 0.f);
            o0[idx] = fmaxf(sc, 0.f);
            o1[idx] = 0.5f * (lr + hr);
            o2[idx] = 0.5f * (hr - lr);
        } else {
            const float bv  = bias[o];
            const float oc  = sc + bv;
            const float mid = sm + bv;
            o0[idx] = -oc;            // -center
            o1[idx] = -(mid + sr);    // -upper
            o2[idx] = -(mid - sr);    // -lower
        }
    }
}

// ---------------------------------------------------------------------------
// Host orchestration (graph-capturable: launches only).
// ---------------------------------------------------------------------------
static inline int cdiv(int a, int b) { return (a + b - 1) / b; }

extern "C" void kernel_launch(void* const* d_in, const int* in_sizes, int n_in,
                              void* d_out, int out_size)
{
    const float* x   = (const float*)d_in[0];
    const float* lo  = (const float*)d_in[1];
    const float* hi  = (const float*)d_in[2];
    const float* w1  = (const float*)d_in[3];
    const float* w2  = (const float*)d_in[4];
    const float* w3  = (const float*)d_in[5];
    const float* w4  = (const float*)d_in[6];
    const float* w5  = (const float*)d_in[7];
    const float* fw1 = (const float*)d_in[8];
    const float* fw2 = (const float*)d_in[9];
    const float* fw3 = (const float*)d_in[10];
    const float* fb3 = (const float*)d_in[11];
    float* out = (float*)d_out;

    cudaFuncSetAttribute(normdist_conv_t<2400, 0, 3>,
                         cudaFuncAttributeMaxDynamicSharedMemorySize, 56 * 1024);
    cudaFuncSetAttribute(normdist_conv_t<2304, 1, 3>,
                         cudaFuncAttributeMaxDynamicSharedMemorySize, 56 * 1024);
    cudaFuncSetAttribute(normdist_conv_t<3456, 1, 3>,
                         cudaFuncAttributeMaxDynamicSharedMemorySize, 56 * 1024);

    float *A, *Bf, *P, *WP;
    cudaGetSymbolAddress((void**)&A,  g_bufA);
    cudaGetSymbolAddress((void**)&Bf, g_bufB);
    cudaGetSymbolAddress((void**)&P,  g_patch);
    cudaGetSymbolAddress((void**)&WP, g_wpad);
    float *A0 = A,  *A1 = A  + VS, *A2 = A  + 2 * VS;
    float *B0 = Bf, *B1 = Bf + VS, *B2 = Bf + 2 * VS;
    float *P0 = P,  *P1 = P  + PS, *P2 = P  + 2 * PS;

    // (1) prep: conv1 patches (c,m,r) from real lower/upper + weight pad
    prep1_kernel<<<cdiv(P1_IM2COL + P1_WPAD, 256), 256>>>(
        x, lo, hi, w1, P0, P1, P2, WP);

    // (2) conv1: -> [16,96,15,15] RAW sums
    normdist_conv_t<148, 0, 4><<<dim3(24, 450), 256, 4 * 148 * 4>>>(
        P0, P1, P2, WP, A0, A1, A2, 225, 96);

    // (3) pool1 (max raw, root8): -> (c,m,r) [16,96,7,7]
    pool3s_kernel<<<cdiv(16 * 96 * 49, 256), 256>>>(
        A0, A1, A2, B0, B1, B2, 16 * 96, 15, 15, 7, 7);

    // (4) window gather k=5,p=2: Fp=2400
    wgather_kernel<96, 7, 5, 2><<<cdiv(16 * 49 * 96, 256), 256>>>(
        B0, B1, B2, P0, P1, P2);

    // (5) conv2: -> [16,256,7,7] RAW sums
    normdist_conv_t<2400, 0, 3><<<dim3(64, 98), 256, 4 * 2400 * 4>>>(
        P0, P1, P2, w2, A0, A1, A2, 49, 256);

    // (6) pool2: -> (c,m,r) [16,256,3,3]
    pool3s_kernel<<<cdiv(16 * 256 * 9, 256), 256>>>(
        A0, A1, A2, B0, B1, B2, 16 * 256, 7, 7, 3, 3);

    // (7) window gather k=3,p=1: Fp=2304
    wgather_kernel<256, 3, 3, 1><<<cdiv(16 * 9 * 256, 256), 256>>>(
        B0, B1, B2, P0, P1, P2);

    // (8) conv3: -> [16,384,3,3] as (c,m,r)
    normdist_conv_t<2304, 1, 3><<<dim3(96, 18), 256, 4 * 2304 * 4>>>(
        P0, P1, P2, w3, A0, A1, A2, 9, 384);

    // (9) window gather k=3,p=1: Fp=3456
    wgather_kernel<384, 3, 3, 1><<<cdiv(16 * 9 * 384, 256), 256>>>(
        A0, A1, A2, P0, P1, P2);

    // (10) conv4: -> [16,384,3,3] as (c,m,r)
    normdist_conv_t<3456, 1, 3><<<dim3(96, 18), 256, 4 * 3456 * 4>>>(
        P0, P1, P2, w4, B0, B1, B2, 9, 384);

    // (11) window gather: Fp=3456
    wgather_kernel<384, 3, 3, 1><<<cdiv(16 * 9 * 384, 256), 256>>>(
        B0, B1, B2, P0, P1, P2);

    // (12) conv5: -> [16,256,3,3] as (c,m,r) == flattened [16,2304]
    normdist_conv_t<3456, 1, 3><<<dim3(64, 18), 256, 4 * 3456 * 4>>>(
        P0, P1, P2, w5, A0, A1, A2, 9, 256);

    // (13) fc1: 2304 -> 1024 (+relu), (c,m,r), 8 batches/warp
    bound_linear8_kernel<<<cdiv(1024 * 2 * 32, 256), 256>>>(
        A0, A1, A2, fw1, (const float*)nullptr, B0, B1, B2, 16, 2304, 1024, 0);
    // (14) fc2: 1024 -> 512 (+relu)
    bound_linear8_kernel<<<cdiv(512 * 2 * 32, 256), 256>>>(
        B0, B1, B2, fw2, (const float*)nullptr, A0, A1, A2, 16, 1024, 512, 0);
    // (15) fc3: 512 -> 10 (+bias): d_out = [-c | -u | -l]
    bound_linear8_kernel<<<cdiv(10 * 2 * 32, 256), 256>>>(
        A0, A1, A2, fw3, fb3, out, out + 160, out + 320, 16, 512, 10, 1);
}

// round 17
// speedup vs baseline: 1.0028x; 1.0001x over previous
#include <cuda_runtime.h>
#include <math.h>

typedef unsigned long long ull;

// ---------------------------------------------------------------------------
// Scratch (device globals; allocations forbidden).
// ---------------------------------------------------------------------------
#define VS 345600
#define PS 1881600
__device__ float g_bufA[3 * VS];
__device__ float g_bufB[3 * VS];
__device__ float g_patch[3 * PS];   // streams: center | mid | rad
__device__ float g_wpad[96 * 148];

#define ABSM 0x7FFFFFFF7FFFFFFFULL
#define M1   0xBF800000BF800000ULL

// ---------------------------------------------------------------------------
// f32x2 packed helpers (sm_103a)
// ---------------------------------------------------------------------------
__device__ __forceinline__ ull pk2(float lo, float hi) {
    ull r; asm("mov.b64 %0, {%1,%2};" : "=l"(r) : "f"(lo), "f"(hi)); return r;
}
__device__ __forceinline__ void upk2(ull v, float& lo, float& hi) {
    asm("mov.b64 {%0,%1}, %2;" : "=f"(lo), "=f"(hi) : "l"(v));
}
__device__ __forceinline__ ull fma2(ull a, ull b, ull c) {
    ull r; asm("fma.rn.f32x2 %0, %1, %2, %3;" : "=l"(r) : "l"(a), "l"(b), "l"(c)); return r;
}
__device__ __forceinline__ ull mul2(ull a, ull b) {
    ull r; asm("mul.rn.f32x2 %0, %1, %2;" : "=l"(r) : "l"(a), "l"(b)); return r;
}
__device__ __forceinline__ ull add2(ull a, ull b) {
    ull r; asm("add.rn.f32x2 %0, %1, %2;" : "=l"(r) : "l"(a), "l"(b)); return r;
}
__device__ __forceinline__ float root8(float s) { return sqrtf(sqrtf(sqrtf(s))); }

// All-packed bound-distance accumulation (13 fma-pipe ops / HALF).
#define HALF(W, VC, MD, RD, AC, AL, AH) {                               \
        ull dc = fma2(W, M1, VC);                                       \
        ull s  = mul2(dc, dc); s = mul2(s, s); AC = fma2(s, s, AC);     \
        ull a  = fma2(W, M1, MD);                                       \
        ull aa = a & ABSM;                                              \
        ull dh = add2(aa, RD);                                          \
        s = mul2(dh, dh); s = mul2(s, s); AH = fma2(s, s, AH);          \
        ull t  = fma2(RD, M1, aa);                                      \
        float t0, t1; upk2(t, t0, t1);                                  \
        ull v  = pk2(fmaxf(t0, 0.f), fmaxf(t1, 0.f));                   \
        s = mul2(v, v); s = mul2(s, s); AL = fma2(s, s, AL); }

// One 4-channel x 4-f-element compute body (weights from smem, fs const).
#define BODY(Q, C4, M4, R4) {                                           \
        const ull c01 = pk2(C4.x, C4.y), c23 = pk2(C4.z, C4.w);         \
        const ull m01 = pk2(M4.x, M4.y), m23 = pk2(M4.z, M4.w);         \
        const ull r01 = pk2(R4.x, R4.y), r23 = pk2(R4.z, R4.w);         \
        _Pragma("unroll")                                               \
        for (int ch = 0; ch < 4; ch++) {                                \
            const float4 wv = wq[(Q) + ch * fs];                        \
            const ull w01 = pk2(wv.x, wv.y), w23 = pk2(wv.z, wv.w);     \
            HALF(w01, c01, m01, r01, A[ch*3], A[ch*3+1], A[ch*3+2]);    \
            HALF(w23, c23, m23, r23, A[ch*3], A[ch*3+1], A[ch*3+2]);    \
        } }

// ---------------------------------------------------------------------------
// prep1: conv1 im2col of (center, mid, rad) from real lower/upper inputs
// (Fp 147->148 zero-pad) + conv1 weight pad.
// ---------------------------------------------------------------------------
#define P1_IM2COL (16 * 225 * 148)
#define P1_WPAD   (96 * 148)
__global__ void __launch_bounds__(256) prep1_kernel(
    const float* __restrict__ ic, const float* __restrict__ il, const float* __restrict__ ih,
    const float* __restrict__ w1,
    float* __restrict__ oc, float* __restrict__ om, float* __restrict__ orr,
    float* __restrict__ wp)
{
    const int idx = blockIdx.x * blockDim.x + threadIdx.x;
    if (idx < P1_IM2COL) {
        const int f  = idx % 148;
        const int bl = idx / 148;
        const int l  = bl % 225;
        const int b  = bl / 225;
        float vc = 0.f, vm = 0.f, vr = 0.f;
        if (f < 147) {
            const int c  = f / 49;
            const int r  = f - c * 49;
            const int ky = r / 7, kx = r - (r / 7) * 7;
            const int oy = l / 15, ox = l - (l / 15) * 15;
            const int iy = oy * 2 - 2 + ky;
            const int ix = ox * 2 - 2 + kx;
            if ((unsigned)iy < 32u && (unsigned)ix < 32u) {
                const int si = ((b * 3 + c) * 32 + iy) * 32 + ix;
                const float lv = il[si], hv = ih[si];
                vc = ic[si]; vm = 0.5f * (lv + hv); vr = 0.5f * (hv - lv);
            }
        }
        oc[idx] = vc; om[idx] = vm; orr[idx] = vr;
    } else if (idx < P1_IM2COL + P1_WPAD) {
        const int j = idx - P1_IM2COL;
        const int f = j % 148, o = j / 148;
        wp[j] = (f < 147) ? w1[o * 147 + f] : 0.f;
    }
}

// ---------------------------------------------------------------------------
// 3x3/s2 maxpool on RAW 8th-power sums -> root8 on pooled maxima (exact)
// -> (c, mid, rad).
// ---------------------------------------------------------------------------
__global__ void __launch_bounds__(256) pool3s_kernel(
    const float* __restrict__ ic, const float* __restrict__ il, const float* __restrict__ ih,
    float* __restrict__ oc, float* __restrict__ om, float* __restrict__ orr,
    int NC, int H, int W, int h, int w)
{
    const int i = blockIdx.x * blockDim.x + threadIdx.x;
    if (i >= NC * h * w) return;
    const int x = i % w;
    const int y = (i / w) % h;
    const int n = i / (w * h);
    const int base = (n * H + y * 2) * W + x * 2;
    float m0 = 0.f, m1 = 0.f, m2 = 0.f;   // sums are >= 0
#pragma unroll
    for (int ky = 0; ky < 3; ky++)
#pragma unroll
        for (int kx = 0; kx < 3; kx++) {
            const int si = base + ky * W + kx;
            m0 = fmaxf(m0, ic[si]);
            m1 = fmaxf(m1, il[si]);
            m2 = fmaxf(m2, ih[si]);
        }
    const float cv = root8(m0);
    const float lv = root8(m1);
    const float hv = root8(m2);
    oc[i] = cv; om[i] = 0.5f * (lv + hv); orr[i] = 0.5f * (hv - lv);
}

// ---------------------------------------------------------------------------
// Window gather: one thread per (bl, c) copies its entire KxK window for all
// three streams (contiguous K*K stores; unrolled; ~2.5x fewer instrs than
// thread-per-element).
// ---------------------------------------------------------------------------
template<int C, int HW, int K, int PAD>
__global__ void __launch_bounds__(256) wgather_kernel(
    const float* __restrict__ ic, const float* __restrict__ im, const float* __restrict__ ir,
    float* __restrict__ oc, float* __restrict__ om, float* __restrict__ orr)
{
    constexpr int KK = K * K;
    constexpr int Fp = C * KK;
    constexpr int L  = HW * HW;
    constexpr int N  = 16 * L * C;
    const int idx = blockIdx.x * blockDim.x + threadIdx.x;
    if (idx >= N) return;
    const int c  = idx % C;
    const int bl = idx / C;
    const int l  = bl % L;
    const int b  = bl / L;
    const int oy = l / HW, ox = l % HW;

    const int plane = (b * C + c) * L;
    const float* sc = ic + plane;
    const float* sm = im + plane;
    const float* sr = ir + plane;
    const size_t dbase = (size_t)bl * Fp + c * KK;
    float* dc = oc + dbase;
    float* dm = om + dbase;
    float* dr = orr + dbase;

#pragma unroll
    for (int ky = 0; ky < K; ky++) {
        const int py = oy - PAD + ky;
        const bool yok = (unsigned)py < (unsigned)HW;
#pragma unroll
        for (int kx = 0; kx < K; kx++) {
            const int px = ox - PAD + kx;
            const bool ok = yok && ((unsigned)px < (unsigned)HW);
            const int si = py * HW + px;
            const int di = ky * K + kx;
            dc[di] = ok ? sc[si] : 0.f;
            dm[di] = ok ? sm[si] : 0.f;
            dr[di] = ok ? sr[si] : 0.f;
        }
    }
}

// ---------------------------------------------------------------------------
// Packed NormDist (L8) conv, fully templated <FP, OUTMODE, MINB>.
// Block = 8 warps, 1 og-quad of weights in smem, 8 bl per block.
// grid = (O/4, BL/8). OUTMODE 0: RAW sums; 1: (c, mid, rad) with root8.
// ---------------------------------------------------------------------------
template<int FP, int OUTMODE, int MINB>
__global__ void __launch_bounds__(256, MINB) normdist_conv_t(
    const float* __restrict__ pc, const float* __restrict__ pm, const float* __restrict__ pr,
    const float* __restrict__ wgt,
    float* __restrict__ o0, float* __restrict__ o1, float* __restrict__ o2,
    int L, int O)
{
    extern __shared__ float swd[];
    constexpr int fs = FP >> 2;
    const int tid = threadIdx.x;
    {
        const float4* src = (const float4*)(wgt + (size_t)blockIdx.x * 4 * FP);
        float4* dst = (float4*)swd;
#pragma unroll
        for (int i = tid; i < FP; i += 256) dst[i] = src[i];
    }
    __syncthreads();

    const int w    = tid >> 5;
    const int lane = tid & 31;
    const int bl   = blockIdx.y * 8 + w;

    const float4* pc4 = (const float4*)(pc + (size_t)bl * FP);
    const float4* pm4 = (const float4*)(pm + (size_t)bl * FP);
    const float4* pr4 = (const float4*)(pr + (size_t)bl * FP);
    const float4* wq  = (const float4*)swd;

    ull A[12];
#pragma unroll
    for (int i = 0; i < 12; i++) A[i] = 0;

    if (fs > 64) {
        int q = lane;
        for (; q + 32 < fs; q += 64) {
            const float4 ca = pc4[q],      ma = pm4[q],      ra = pr4[q];
            const float4 cb = pc4[q + 32], mb = pm4[q + 32], rb = pr4[q + 32];
            BODY(q, ca, ma, ra);
            BODY(q + 32, cb, mb, rb);
        }
        if (q < fs) {
            const float4 ca = pc4[q], ma = pm4[q], ra = pr4[q];
            BODY(q, ca, ma, ra);
        }
    } else {
#pragma unroll
        for (int qq = 0; qq < (fs + 31) / 32; qq++) {
            const int q = qq * 32 + lane;
            if (q < fs) {
                const float4 ca = pc4[q], ma = pm4[q], ra = pr4[q];
                BODY(q, ca, ma, ra);
            }
        }
    }

    float r[12];
#pragma unroll
    for (int i = 0; i < 12; i++) {
        float x0, x1; upk2(A[i], x0, x1); r[i] = x0 + x1;
    }
#pragma unroll
    for (int off = 16; off; off >>= 1)
#pragma unroll
        for (int i = 0; i < 12; i++)
            r[i] += __shfl_xor_sync(0xffffffffu, r[i], off);

    if (lane < 4) {
        const int b = bl / L, l = bl - (bl / L) * L;
        const int o = blockIdx.x * 4 + lane;
        const size_t ob = ((size_t)b * O + o) * L + l;
        if (OUTMODE == 0) {
            o0[ob] = r[3 * lane];
            o1[ob] = r[3 * lane + 1];
            o2[ob] = r[3 * lane + 2];
        } else {
            const float oc = root8(r[3 * lane]);
            const float ol = root8(r[3 * lane + 1]);
            const float oh = root8(r[3 * lane + 2]);
            o0[ob] = oc;
            o1[ob] = 0.5f * (ol + oh);
            o2[ob] = 0.5f * (oh - ol);
        }
    }
}

// ---------------------------------------------------------------------------
// Interval-bound linear on (c, m, r) streams, 8 batches per warp
// (halves weight traffic vs 4). mode 0: relu, outputs (c, m, r);
// mode 1: final (-c, -u, -l).
// ---------------------------------------------------------------------------
__global__ void __launch_bounds__(256) bound_linear8_kernel(
    const float* __restrict__ inc, const float* __restrict__ inm, const float* __restrict__ inr,
    const float* __restrict__ Wm, const float* __restrict__ bias,
    float* __restrict__ o0, float* __restrict__ o1, float* __restrict__ o2,
    int B, int IN, int OUT, int mode)
{
    const int warp = (blockIdx.x * blockDim.x + threadIdx.x) >> 5;
    const int lane = threadIdx.x & 31;
    const int BG = B >> 3;
    if (warp >= OUT * BG) return;
    const int o  = warp % OUT;
    const int bg = warp / OUT;
    const int b0 = bg * 8;

    const float4* w4 = (const float4*)(Wm + (size_t)o * IN);
    const float4* c4 = (const float4*)(inc + (size_t)b0 * IN);
    const float4* m4 = (const float4*)(inm + (size_t)b0 * IN);
    const float4* r4 = (const float4*)(inr + (size_t)b0 * IN);
    const int n4 = IN >> 2;

    float r[24];
#pragma unroll
    for (int i = 0; i < 24; i++) r[i] = 0.f;

    for (int k = lane; k < n4; k += 32) {
        const float4 wv = w4[k];
        const float awx = fabsf(wv.x), awy = fabsf(wv.y), awz = fabsf(wv.z), aww = fabsf(wv.w);
#pragma unroll
        for (int j = 0; j < 8; j++) {
            const float4 cv = c4[k + (size_t)j * n4];
            const float4 mv = m4[k + (size_t)j * n4];
            const float4 rv = r4[k + (size_t)j * n4];
            float sc = r[j * 3], sm = r[j * 3 + 1], sr = r[j * 3 + 2];
            sc = fmaf(cv.x, wv.x, sc); sc = fmaf(cv.y, wv.y, sc);
            sc = fmaf(cv.z, wv.z, sc); sc = fmaf(cv.w, wv.w, sc);
            sm = fmaf(mv.x, wv.x, sm); sm = fmaf(mv.y, wv.y, sm);
            sm = fmaf(mv.z, wv.z, sm); sm = fmaf(mv.w, wv.w, sm);
            sr = fmaf(rv.x, awx, sr); sr = fmaf(rv.y, awy, sr);
            sr = fmaf(rv.z, awz, sr); sr = fmaf(rv.w, aww, sr);
            r[j * 3] = sc; r[j * 3 + 1] = sm; r[j * 3 + 2] = sr;
        }
    }
#pragma unroll
    for (int off = 16; off; off >>= 1)
#pragma unroll
        for (int i = 0; i < 24; i++)
            r[i] += __shfl_xor_sync(0xffffffffu, r[i], off);

    if (lane < 8) {
        const int b = b0 + lane;
        const float sc = r[lane * 3], sm = r[lane * 3 + 1], sr = r[lane * 3 + 2];
        const size_t idx = (size_t)b * OUT + o;
        if (mode == 0) {
            const float lr = fmaxf(sm - sr, 0.f);
            const float hr = fmaxf(sm + sr, 0.f);
            o0[idx] = fmaxf(sc, 0.f);
            o1[idx] = 0.5f * (lr + hr);
            o2[idx] = 0.5f * (hr - lr);
        } else {
            const float bv  = bias[o];
            const float oc  = sc + bv;
            const float mid = sm + bv;
            o0[idx] = -oc;            // -center
            o1[idx] = -(mid + sr);    // -upper
            o2[idx] = -(mid - sr);    // -lower
        }
    }
}

// ---------------------------------------------------------------------------
// Host orchestration (graph-capturable: launches only).
// ---------------------------------------------------------------------------
static inline int cdiv(int a, int b) { return (a + b - 1) / b; }

extern "C" void kernel_launch(void* const* d_in, const int* in_sizes, int n_in,
                              void* d_out, int out_size)
{
    const float* x   = (const float*)d_in[0];
    const float* lo  = (const float*)d_in[1];
    const float* hi  = (const float*)d_in[2];
    const float* w1  = (const float*)d_in[3];
    const float* w2  = (const float*)d_in[4];
    const float* w3  = (const float*)d_in[5];
    const float* w4  = (const float*)d_in[6];
    const float* w5  = (const float*)d_in[7];
    const float* fw1 = (const float*)d_in[8];
    const float* fw2 = (const float*)d_in[9];
    const float* fw3 = (const float*)d_in[10];
    const float* fb3 = (const float*)d_in[11];
    float* out = (float*)d_out;

    cudaFuncSetAttribute(normdist_conv_t<2400, 0, 3>,
                         cudaFuncAttributeMaxDynamicSharedMemorySize, 56 * 1024);
    cudaFuncSetAttribute(normdist_conv_t<2304, 1, 3>,
                         cudaFuncAttributeMaxDynamicSharedMemorySize, 56 * 1024);
    cudaFuncSetAttribute(normdist_conv_t<3456, 1, 3>,
                         cudaFuncAttributeMaxDynamicSharedMemorySize, 56 * 1024);

    float *A, *Bf, *P, *WP;
    cudaGetSymbolAddress((void**)&A,  g_bufA);
    cudaGetSymbolAddress((void**)&Bf, g_bufB);
    cudaGetSymbolAddress((void**)&P,  g_patch);
    cudaGetSymbolAddress((void**)&WP, g_wpad);
    float *A0 = A,  *A1 = A  + VS, *A2 = A  + 2 * VS;
    float *B0 = Bf, *B1 = Bf + VS, *B2 = Bf + 2 * VS;
    float *P0 = P,  *P1 = P  + PS, *P2 = P  + 2 * PS;

    // (1) prep: conv1 patches (c,m,r) from real lower/upper + weight pad
    prep1_kernel<<<cdiv(P1_IM2COL + P1_WPAD, 256), 256>>>(
        x, lo, hi, w1, P0, P1, P2, WP);

    // (2) conv1: -> [16,96,15,15] RAW sums
    normdist_conv_t<148, 0, 4><<<dim3(24, 450), 256, 4 * 148 * 4>>>(
        P0, P1, P2, WP, A0, A1, A2, 225, 96);

    // (3) pool1 (max raw, root8): -> (c,m,r) [16,96,7,7]
    pool3s_kernel<<<cdiv(16 * 96 * 49, 256), 256>>>(
        A0, A1, A2, B0, B1, B2, 16 * 96, 15, 15, 7, 7);

    // (4) window gather k=5,p=2: Fp=2400
    wgather_kernel<96, 7, 5, 2><<<cdiv(16 * 49 * 96, 256), 256>>>(
        B0, B1, B2, P0, P1, P2);

    // (5) conv2: -> [16,256,7,7] RAW sums
    normdist_conv_t<2400, 0, 3><<<dim3(64, 98), 256, 4 * 2400 * 4>>>(
        P0, P1, P2, w2, A0, A1, A2, 49, 256);

    // (6) pool2: -> (c,m,r) [16,256,3,3]
    pool3s_kernel<<<cdiv(16 * 256 * 9, 256), 256>>>(
        A0, A1, A2, B0, B1, B2, 16 * 256, 7, 7, 3, 3);

    // (7) window gather k=3,p=1: Fp=2304
    wgather_kernel<256, 3, 3, 1><<<cdiv(16 * 9 * 256, 256), 256>>>(
        B0, B1, B2, P0, P1, P2);

    // (8) conv3: -> [16,384,3,3] as (c,m,r)
    normdist_conv_t<2304, 1, 3><<<dim3(96, 18), 256, 4 * 2304 * 4>>>(
        P0, P1, P2, w3, A0, A1, A2, 9, 384);

    // (9) window gather k=3,p=1: Fp=3456
    wgather_kernel<384, 3, 3, 1><<<cdiv(16 * 9 * 384, 256), 256>>>(
        A0, A1, A2, P0, P1, P2);

    // (10) conv4: -> [16,384,3,3] as (c,m,r)
    normdist_conv_t<3456, 1, 3><<<dim3(96, 18), 256, 4 * 3456 * 4>>>(
        P0, P1, P2, w4, B0, B1, B2, 9, 384);

    // (11) window gather: Fp=3456
    wgather_kernel<384, 3, 3, 1><<<cdiv(16 * 9 * 384, 256), 256>>>(
        B0, B1, B2, P0, P1, P2);

    // (12) conv5: -> [16,256,3,3] as (c,m,r) == flattened [16,2304]
    normdist_conv_t<3456, 1, 3><<<dim3(64, 18), 256, 4 * 3456 * 4>>>(
        P0, P1, P2, w5, A0, A1, A2, 9, 256);

    // (13) fc1: 2304 -> 1024 (+relu), (c,m,r), 8 batches/warp
    bound_linear8_kernel<<<cdiv(1024 * 2 * 32, 256), 256>>>(
        A0, A1, A2, fw1, (const float*)nullptr, B0, B1, B2, 16, 2304, 1024, 0);
    // (14) fc2: 1024 -> 512 (+relu)
    bound_linear8_kernel<<<cdiv(512 * 2 * 32, 256), 256>>>(
        B0, B1, B2, fw2, (const float*)nullptr, A0, A1, A2, 16, 1024, 512, 0);
    // (15) fc3: 512 -> 10 (+bias): d_out = [-c | -u | -l]
    bound_linear8_kernel<<<cdiv(10 * 2 * 32, 256), 256>>>(
        A0, A1, A2, fw3, fb3, out, out + 160, out + 320, 16, 512, 10, 1);
}